// round 13
// baseline (speedup 1.0000x reference)
#include <cuda_runtime.h>
#include <cuda_fp16.h>
#include <math.h>
#include <stdint.h>

#define NSAMP 65536
#define HID   512
#define NGATE 2048
#define DIN   259
#define BM 128
#define BN 128
#define BK 32
#define RS 20              // smem row stride in words (16 data + 4 pad)
#define ABUF (BM * RS * 4)
#define BBUF (BN * RS * 4)

// ------------------------- scratch -------------------------
__device__ __half g_Gc [(size_t)NSAMP * NGATE];   // gate-interleaved [r][j*4+gate], fp16
__device__ __half g_h  [(size_t)NSAMP * HID];
__device__ __half g_h2 [(size_t)NSAMP * HID];
__device__ float  g_c  [(size_t)NSAMP * HID];
__device__ float  g_xyz[NSAMP * 3];
__device__ __half g_code[(size_t)NSAMP * 256];
__device__ __half g_wih [(size_t)NGATE * 256];
__device__ __half g_whh [(size_t)NGATE * HID];
__device__ float  g_wx  [HID * 16];               // [unit][gate*4 + k], k<3 used
__device__ __half g_act0[(size_t)NSAMP * 256];
__device__ __half g_act1[(size_t)NSAMP * 256];
__device__ float  g_w0  [256 * 3];
__device__ __half g_wm  [4 * 256 * 256];

__device__ __forceinline__ float sigm(float x) { return 1.f / (1.f + __expf(-x)); }
__device__ __forceinline__ void cp16(uint32_t d, const void* s) {
    asm volatile("cp.async.cg.shared.global [%0], [%1], 16;" :: "r"(d), "l"(s) : "memory");
}
__device__ __forceinline__ void mma16(float* d, const unsigned* a, unsigned b0, unsigned b1) {
    asm volatile(
        "mma.sync.aligned.m16n8k16.row.col.f32.f16.f16.f32 "
        "{%0,%1,%2,%3}, {%4,%5,%6,%7}, {%8,%9}, {%0,%1,%2,%3};"
        : "+f"(d[0]), "+f"(d[1]), "+f"(d[2]), "+f"(d[3])
        : "r"(a[0]), "r"(a[1]), "r"(a[2]), "r"(a[3]), "r"(b0), "r"(b1));
}
#define LDSM4(R, ADDR)                                                         \
    asm volatile("ldmatrix.sync.aligned.m8n8.x4.shared.b16 {%0,%1,%2,%3}, [%4];" \
        : "=r"((R)[0]), "=r"((R)[1]), "=r"((R)[2]), "=r"((R)[3]) : "r"(ADDR))

// =====================================================================
// FP16 GEMM (fp32 accum), 256 threads = 8 warps (4m x 2n), warp tile
// 32x64, block tile 128x128, BK=32, pair-granule double buffering
// (one __syncthreads per TWO K-tiles), 2 CTAs/SM.
// MODE 0: Gc build (fp16, gate-interleaved) + step-0 cell init
// MODE 1: LSTM step s>=1    MODE 2: decoder relu layer
// =====================================================================
template<int MODE>
__global__ void __launch_bounds__(256, 2) gemm_h(
    const __half* __restrict__ A, int lda,
    const __half* __restrict__ B, int ldb,
    __half* __restrict__ Ch, int ldc, int kIters,
    const float* __restrict__ bias, const float* __restrict__ bias2,
    const float* __restrict__ xyz,
    __half* __restrict__ Gc,
    float* __restrict__ cst, __half* __restrict__ hout)
{
    extern __shared__ uint32_t smw[];
    const int tid = threadIdx.x, lane = tid & 31, wid = tid >> 5;
    const int wm = wid >> 1, wn = wid & 1;
    const int g = lane >> 2, t = lane & 3;
    const int m0 = blockIdx.y * BM;
    const int n0 = blockIdx.x * BN;
    const int j0 = blockIdx.x * 32;

    const int arow = tid >> 1, seg = tid & 1;
    int brow;
    if (MODE == 0 || MODE == 1) {
        int w = arow >> 6, cw = arow & 63;
        brow = (cw >> 4) * HID + j0 + (cw & 15) + (w << 4);
    } else brow = n0 + arow;

    const __half* aptr = A + (size_t)(m0 + arow) * lda + seg * 16;
    const __half* bptr = B + (size_t)brow * ldb + seg * 16;

    const uint32_t asb = (uint32_t)__cvta_generic_to_shared(smw);
    const uint32_t bsb = asb + 4 * ABUF;
    const uint32_t aoff = asb + arow * (RS * 4) + seg * 32;
    const uint32_t boff = bsb + arow * (RS * 4) + seg * 32;

    const int lr = lane & 15, lw = (lane >> 4) * 16;
    uint32_t aadr[2], badr[4];
#pragma unroll
    for (int mt = 0; mt < 2; mt++)
        aadr[mt] = asb + (uint32_t)((wm * 32 + mt * 16 + lr) * RS * 4) + lw;
#pragma unroll
    for (int p = 0; p < 4; p++)
        badr[p] = bsb + (uint32_t)((wn * 64 + p * 16 + lr) * RS * 4) + lw;

    float acc[2][8][4];
#pragma unroll
    for (int i = 0; i < 2; i++)
#pragma unroll
        for (int j = 0; j < 8; j++)
#pragma unroll
            for (int k = 0; k < 4; k++) acc[i][j][k] = 0.f;

    // load tile IT into buffer BUF (0..3)
#define LOADTILE(IT, BUF)                                                     \
    do {                                                                      \
        cp16(aoff + (BUF) * ABUF, aptr + (IT) * BK);                          \
        cp16(aoff + (BUF) * ABUF + 16, aptr + (IT) * BK + 8);                 \
        cp16(boff + (BUF) * BBUF, bptr + (IT) * BK);                          \
        cp16(boff + (BUF) * BBUF + 16, bptr + (IT) * BK + 8);                 \
    } while (0)

    const int P = kIters >> 1;      // pairs (kIters is even: 8 or 16)

    // prologue: pair 0 -> buffers 0,1
    LOADTILE(0, 0);
    LOADTILE(1, 1);
    asm volatile("cp.async.commit_group;" ::: "memory");

    for (int S = 0; S < P; ++S) {
        asm volatile("cp.async.wait_group 0;" ::: "memory");
        __syncthreads();
        if (S + 1 < P) {
            const int half = ((S + 1) & 1) * 2;
            LOADTILE(2 * S + 2, half);
            LOADTILE(2 * S + 3, half + 1);
            asm volatile("cp.async.commit_group;" ::: "memory");
        }
#pragma unroll
        for (int tt = 0; tt < 2; tt++) {
            const int buf = (S & 1) * 2 + tt;
            const uint32_t ao = buf * ABUF, bo = buf * BBUF;
#pragma unroll
            for (int ks = 0; ks < 2; ks++) {
                unsigned af[2][4];
                LDSM4(af[0], aadr[0] + ao + ks * 32);
                LDSM4(af[1], aadr[1] + ao + ks * 32);
#pragma unroll
                for (int p = 0; p < 4; p++) {
                    unsigned bb[4];
                    LDSM4(bb, badr[p] + bo + ks * 32);
                    mma16(acc[0][2 * p],     af[0], bb[0], bb[2]);
                    mma16(acc[0][2 * p + 1], af[0], bb[1], bb[3]);
                    mma16(acc[1][2 * p],     af[1], bb[0], bb[2]);
                    mma16(acc[1][2 * p + 1], af[1], bb[1], bb[3]);
                }
            }
        }
    }
#undef LOADTILE

    // ----------------- epilogue -----------------
    if (MODE == 0 || MODE == 1) {
#pragma unroll
        for (int q = 0; q < 2; q++) {
            const int jc = j0 + wn * 16 + q * 8 + 2 * t;
            float4 wt[4][2];
            float bi[4][2];
#pragma unroll
            for (int e = 0; e < 2; e++) {
                const float4* wxp = (const float4*)(g_wx + (jc + e) * 16);
#pragma unroll
                for (int gt = 0; gt < 4; gt++) {
                    wt[gt][e] = wxp[gt];
                    if (MODE == 0)
                        bi[gt][e] = bias[gt * HID + jc + e] + bias2[gt * HID + jc + e];
                }
            }
#pragma unroll
            for (int mt = 0; mt < 2; mt++)
#pragma unroll
                for (int rr = 0; rr < 2; rr++) {
                    int r = m0 + wm * 32 + mt * 16 + g + rr * 8;
                    float x0 = xyz[r * 3], x1 = xyz[r * 3 + 1], x2 = xyz[r * 3 + 2];
                    float2 cn; __half2 hn;
                    __half* gcp = Gc + (size_t)r * NGATE + jc * 4;
                    if (MODE == 0) {
                        __align__(16) __half hg[8];
#pragma unroll
                        for (int e = 0; e < 2; e++) {
                            int a = rr * 2 + e;
                            float gcv[4], gate[4];
#pragma unroll
                            for (int gt = 0; gt < 4; gt++) {
                                gcv[gt] = acc[mt][2 * gt + q][a] + bi[gt][e];
                                gate[gt] = gcv[gt] + x0 * wt[gt][e].x
                                         + x1 * wt[gt][e].y + x2 * wt[gt][e].z;
                                hg[e * 4 + gt] = __float2half_rn(gcv[gt]);
                            }
                            float c2 = sigm(gate[0]) * tanhf(gate[2]);
                            __half h2 = __float2half_rn(sigm(gate[3]) * tanhf(c2));
                            if (e) { cn.y = c2; hn.y = h2; } else { cn.x = c2; hn.x = h2; }
                        }
                        *(uint4*)gcp = *(const uint4*)hg;
                    } else {
                        __align__(16) __half hg[8];
                        *(uint4*)hg = *(const uint4*)gcp;
                        float2 co = *(const float2*)(cst + (size_t)r * HID + jc);
#pragma unroll
                        for (int e = 0; e < 2; e++) {
                            int a = rr * 2 + e;
                            float iv = acc[mt][0 + q][a] + __half2float(hg[e * 4 + 0])
                                     + x0 * wt[0][e].x + x1 * wt[0][e].y + x2 * wt[0][e].z;
                            float fv = acc[mt][2 + q][a] + __half2float(hg[e * 4 + 1])
                                     + x0 * wt[1][e].x + x1 * wt[1][e].y + x2 * wt[1][e].z;
                            float gv = acc[mt][4 + q][a] + __half2float(hg[e * 4 + 2])
                                     + x0 * wt[2][e].x + x1 * wt[2][e].y + x2 * wt[2][e].z;
                            float ov = acc[mt][6 + q][a] + __half2float(hg[e * 4 + 3])
                                     + x0 * wt[3][e].x + x1 * wt[3][e].y + x2 * wt[3][e].z;
                            float cold = e ? co.y : co.x;
                            float c2 = sigm(fv) * cold + sigm(iv) * tanhf(gv);
                            __half h2 = __float2half_rn(sigm(ov) * tanhf(c2));
                            if (e) { cn.y = c2; hn.y = h2; } else { cn.x = c2; hn.x = h2; }
                        }
                    }
                    *(float2*)(cst + (size_t)r * HID + jc) = cn;
                    *(__half2*)(hout + (size_t)r * HID + jc) = hn;
                }
        }
    } else {
#pragma unroll
        for (int mt = 0; mt < 2; mt++)
#pragma unroll
            for (int nt = 0; nt < 8; nt++) {
                int c = n0 + wn * 64 + nt * 8 + 2 * t;
                float b0v = bias[c], b1v = bias[c + 1];
#pragma unroll
                for (int rr = 0; rr < 2; rr++) {
                    int r = m0 + wm * 32 + mt * 16 + g + rr * 8;
                    __half2 o;
                    o.x = __float2half_rn(fmaxf(acc[mt][nt][rr * 2 + 0] + b0v, 0.f));
                    o.y = __float2half_rn(fmaxf(acc[mt][nt][rr * 2 + 1] + b1v, 0.f));
                    *(__half2*)(Ch + (size_t)r * ldc + c) = o;
                }
            }
    }
}

// ------------------------- prep kernels -------------------------
__global__ void extract_code(const float* __restrict__ input,
                             const float* __restrict__ W_ih)
{
    int m = blockIdx.x, k = threadIdx.x;
    g_code[(size_t)m * 256 + k] = __float2half_rn(input[(size_t)m * DIN + k]);
    if (k < 3) g_xyz[m * 3 + k] = input[(size_t)m * DIN + 256 + k];
    if (m < HID && k < 16) {
        int gt = k >> 2, kk = k & 3;
        g_wx[m * 16 + gt * 4 + kk] =
            (kk < 3) ? W_ih[(size_t)(gt * HID + m) * DIN + 256 + kk] : 0.f;
    }
}
__global__ void prep_weights(const float* __restrict__ W_ih, const float* __restrict__ W_hh)
{
    int r = blockIdx.x, t = threadIdx.x;
    g_wih[(size_t)r * 256 + t] = __float2half_rn(W_ih[(size_t)r * DIN + t]);
    g_whh[(size_t)r * HID + t]       = __float2half_rn(W_hh[(size_t)r * HID + t]);
    g_whh[(size_t)r * HID + 256 + t] = __float2half_rn(W_hh[(size_t)r * HID + 256 + t]);
}
struct WnArgs { const float* v[5]; const float* g[5]; };
__global__ void wnorm_all(WnArgs wa)
{
    int layer = blockIdx.x >> 8, row = blockIdx.x & 255;
    int din = (layer == 0) ? 3 : 256;
    const float* vr = wa.v[layer] + (size_t)row * din;
    float s = 0.f;
    for (int k = threadIdx.x; k < din; k += blockDim.x) { float x = vr[k]; s += x * x; }
    __shared__ float red[4];
#pragma unroll
    for (int o = 16; o; o >>= 1) s += __shfl_xor_sync(0xffffffffu, s, o);
    if ((threadIdx.x & 31) == 0) red[threadIdx.x >> 5] = s;
    __syncthreads();
    float scale = wa.g[layer][row] / sqrtf(red[0] + red[1] + red[2] + red[3]);
    if (layer == 0) {
        for (int k = threadIdx.x; k < din; k += blockDim.x)
            g_w0[(size_t)row * din + k] = vr[k] * scale;
    } else {
        __half* w = g_wm + (size_t)(layer - 1) * 256 * 256 + (size_t)row * 256;
        for (int k = threadIdx.x; k < din; k += blockDim.x)
            w[k] = __float2half_rn(vr[k] * scale);
    }
}

// ------------------------- affine + xyz update -------------------------
__global__ __launch_bounds__(256) void affine_xyz(const __half* __restrict__ h_in,
                                                  const float* __restrict__ W_aff,
                                                  const float* __restrict__ b_aff)
{
    __shared__ float sW[6 * HID];
    for (int i = threadIdx.x; i < 6 * HID; i += 256) sW[i] = W_aff[i];
    __syncthreads();
    int warp = threadIdx.x >> 5, lane = threadIdx.x & 31;
    int m = blockIdx.x * 8 + warp;
    const __half* h = h_in + (size_t)m * HID;
    float p0 = 0, p1 = 0, p2 = 0, p3 = 0, p4 = 0, p5 = 0;
    for (int k = lane; k < HID; k += 32) {
        float hv = __half2float(h[k]);
        p0 += sW[k] * hv;           p1 += sW[HID + k] * hv;
        p2 += sW[2 * HID + k] * hv; p3 += sW[3 * HID + k] * hv;
        p4 += sW[4 * HID + k] * hv; p5 += sW[5 * HID + k] * hv;
    }
#pragma unroll
    for (int o = 16; o; o >>= 1) {
        p0 += __shfl_xor_sync(0xffffffffu, p0, o);
        p1 += __shfl_xor_sync(0xffffffffu, p1, o);
        p2 += __shfl_xor_sync(0xffffffffu, p2, o);
        p3 += __shfl_xor_sync(0xffffffffu, p3, o);
        p4 += __shfl_xor_sync(0xffffffffu, p4, o);
        p5 += __shfl_xor_sync(0xffffffffu, p5, o);
    }
    if (lane == 0) {
        float a0 = p0 + b_aff[0], a1 = p1 + b_aff[1], a2 = p2 + b_aff[2];
        float a3 = p3 + b_aff[3], a4 = p4 + b_aff[4], a5 = p5 + b_aff[5];
        float x0 = g_xyz[m * 3], x1 = g_xyz[m * 3 + 1], x2 = g_xyz[m * 3 + 2];
        g_xyz[m * 3 + 0] = a3 + (1.f + a0) * x0;
        g_xyz[m * 3 + 1] = a4 + (1.f + a1) * x1;
        g_xyz[m * 3 + 2] = a5 + (1.f + a2) * x2;
    }
}

// ------------------------- decoder layer 0 / final dot -------------------------
__global__ __launch_bounds__(256) void dec0(const float* __restrict__ b0)
{
    __shared__ float sw[768];
    __shared__ float sb[256];
    for (int i = threadIdx.x; i < 768; i += 256) sw[i] = g_w0[i];
    sb[threadIdx.x] = b0[threadIdx.x];
    __syncthreads();
    size_t idx = (size_t)blockIdx.x * 256 + threadIdx.x;
    int m = (int)(idx >> 8), i = (int)(idx & 255);
    float v = sw[i * 3] * g_xyz[m * 3] + sw[i * 3 + 1] * g_xyz[m * 3 + 1]
            + sw[i * 3 + 2] * g_xyz[m * 3 + 2] + sb[i];
    g_act0[idx] = __float2half_rn(fmaxf(v, 0.f));
}
__global__ __launch_bounds__(256) void dec5(const float* __restrict__ W5,
                                            const float* __restrict__ b5,
                                            const __half* __restrict__ x,
                                            float* __restrict__ out)
{
    __shared__ float sw[256];
    sw[threadIdx.x] = W5[threadIdx.x];
    __syncthreads();
    int warp = threadIdx.x >> 5, lane = threadIdx.x & 31;
    int m = blockIdx.x * 8 + warp;
    const __half* xr = x + (size_t)m * 256;
    float s = 0.f;
    for (int k = lane; k < 256; k += 32) s += __half2float(xr[k]) * sw[k];
#pragma unroll
    for (int o = 16; o; o >>= 1) s += __shfl_xor_sync(0xffffffffu, s, o);
    if (lane == 0) out[m] = s + b5[0];
}

// ------------------------- host launcher -------------------------
extern "C" void kernel_launch(void* const* d_in, const int* in_sizes, int n_in,
                              void* d_out, int out_size)
{
    const float* input = (const float*)d_in[0];
    const float* W_ih  = (const float*)d_in[1];
    const float* b_ih  = (const float*)d_in[2];
    const float* W_hh  = (const float*)d_in[3];
    const float* b_hh  = (const float*)d_in[4];
    const float* W_aff = (const float*)d_in[5];
    const float* b_aff = (const float*)d_in[6];
    WnArgs wa;
    const float* bb[5];
    for (int l = 0; l < 5; l++) {
        wa.v[l] = (const float*)d_in[7 + 3 * l];
        wa.g[l] = (const float*)d_in[8 + 3 * l];
        bb[l]   = (const float*)d_in[9 + 3 * l];
    }
    const float* W5 = (const float*)d_in[22];
    const float* b5 = (const float*)d_in[23];

    float *cst, *xyz;
    __half *Gc, *h0, *h1, *codep, *wihp, *whhp, *a0p, *a1p, *wmp;
    cudaGetSymbolAddress((void**)&Gc,    g_Gc);
    cudaGetSymbolAddress((void**)&h0,    g_h);
    cudaGetSymbolAddress((void**)&h1,    g_h2);
    cudaGetSymbolAddress((void**)&cst,   g_c);
    cudaGetSymbolAddress((void**)&xyz,   g_xyz);
    cudaGetSymbolAddress((void**)&codep, g_code);
    cudaGetSymbolAddress((void**)&wihp,  g_wih);
    cudaGetSymbolAddress((void**)&whhp,  g_whh);
    cudaGetSymbolAddress((void**)&a0p,   g_act0);
    cudaGetSymbolAddress((void**)&a1p,   g_act1);
    cudaGetSymbolAddress((void**)&wmp,   g_wm);

    const int SMEM = 4 * (ABUF + BBUF);   // 81920 B per CTA
    cudaFuncSetAttribute(gemm_h<0>, cudaFuncAttributeMaxDynamicSharedMemorySize, SMEM);
    cudaFuncSetAttribute(gemm_h<1>, cudaFuncAttributeMaxDynamicSharedMemorySize, SMEM);
    cudaFuncSetAttribute(gemm_h<2>, cudaFuncAttributeMaxDynamicSharedMemorySize, SMEM);

    extract_code<<<NSAMP, 256>>>(input, W_ih);
    prep_weights<<<NGATE, 256>>>(W_ih, W_hh);
    wnorm_all<<<1280, 128>>>(wa);

    // launch 3 (profiled): fused Gc GEMM + step-0 cell init
    gemm_h<0><<<dim3(NGATE / BN, NSAMP / BM), 256, SMEM>>>(
        codep, 256, wihp, 256, nullptr, 0, 256 / BK,
        b_ih, b_hh, xyz, Gc, cst, h0);

    affine_xyz<<<NSAMP / 8, 256>>>(h0, W_aff, b_aff);

    __half* hb[2] = { h0, h1 };
    for (int s = 1; s < 8; s++) {
        const __half* hin = hb[(s - 1) & 1];
        __half* hnew = hb[s & 1];
        gemm_h<1><<<dim3(HID / 32, NSAMP / BM), 256, SMEM>>>(
            hin, HID, whhp, HID, nullptr, 0, HID / BK,
            nullptr, nullptr, xyz, Gc, cst, hnew);
        affine_xyz<<<NSAMP / 8, 256>>>(hnew, W_aff, b_aff);
    }

    dec0<<<NSAMP, 256>>>(bb[0]);
    const __half* bufin = a0p;
    __half* bufout = a1p;
    for (int l = 1; l < 5; l++) {
        gemm_h<2><<<dim3(256 / BN, NSAMP / BM), 256, SMEM>>>(
            bufin, 256, wmp + (size_t)(l - 1) * 256 * 256, 256,
            bufout, 256, 256 / BK,
            bb[l], nullptr, nullptr, nullptr, nullptr, nullptr);
        const __half* tmp = bufout; bufout = (__half*)bufin; bufin = tmp;
    }
    dec5<<<NSAMP / 8, 256>>>(W5, b5, bufin, (float*)d_out);
}

// round 14
// speedup vs baseline: 1.1107x; 1.1107x over previous
#include <cuda_runtime.h>
#include <cuda_fp16.h>
#include <math.h>
#include <stdint.h>

#define NSAMP 65536
#define HID   512
#define NGATE 2048
#define DIN   259
#define BM 128
#define BN 128
#define BK 32
#define RS 20              // smem row stride in words (16 data + 4 pad)
#define ABUF (BM * RS * 4)
#define BBUF (BN * RS * 4)
#define NSTAGE 4

// ------------------------- scratch -------------------------
__device__ __half g_Gc [(size_t)NSAMP * NGATE];   // gate-interleaved [r][j*4+gate], fp16
__device__ __half g_h  [(size_t)NSAMP * HID];
__device__ __half g_h2 [(size_t)NSAMP * HID];
__device__ float  g_c  [(size_t)NSAMP * HID];
__device__ float  g_xyz[NSAMP * 3];
__device__ __half g_code[(size_t)NSAMP * 256];
__device__ __half g_wih [(size_t)NGATE * 256];
__device__ __half g_whh [(size_t)NGATE * HID];
__device__ float  g_wx  [HID * 16];               // [unit][gate*4 + k], k<3 used
__device__ __half g_act0[(size_t)NSAMP * 256];
__device__ __half g_act1[(size_t)NSAMP * 256];
__device__ float  g_w0  [256 * 3];
__device__ __half g_wm  [4 * 256 * 256];

__device__ __forceinline__ float sigm(float x) { return 1.f / (1.f + __expf(-x)); }
__device__ __forceinline__ void cp16(uint32_t d, const void* s) {
    asm volatile("cp.async.cg.shared.global [%0], [%1], 16;" :: "r"(d), "l"(s) : "memory");
}
__device__ __forceinline__ void mma16(float* d, const unsigned* a, unsigned b0, unsigned b1) {
    asm volatile(
        "mma.sync.aligned.m16n8k16.row.col.f32.f16.f16.f32 "
        "{%0,%1,%2,%3}, {%4,%5,%6,%7}, {%8,%9}, {%0,%1,%2,%3};"
        : "+f"(d[0]), "+f"(d[1]), "+f"(d[2]), "+f"(d[3])
        : "r"(a[0]), "r"(a[1]), "r"(a[2]), "r"(a[3]), "r"(b0), "r"(b1));
}
#define LDSM4(R, ADDR)                                                         \
    asm volatile("ldmatrix.sync.aligned.m8n8.x4.shared.b16 {%0,%1,%2,%3}, [%4];" \
        : "=r"((R)[0]), "=r"((R)[1]), "=r"((R)[2]), "=r"((R)[3]) : "r"(ADDR))

// =====================================================================
// FP16 GEMM (fp32 accum), 256 threads = 8 warps (4m x 2n), warp tile
// 32x64, block tile 128x128, BK=32, 4-stage cp.async (wait_group 2),
// 2 CTAs/SM, fully-unrolled K loop (KITERS compile-time).
// MODE 0: Gc build (fp16, gate-interleaved) + step-0 cell init
// MODE 1: LSTM step s>=1    MODE 2: decoder relu layer
// =====================================================================
template<int MODE, int KITERS>
__global__ void __launch_bounds__(256, 2) gemm_h(
    const __half* __restrict__ A, int lda,
    const __half* __restrict__ B, int ldb,
    __half* __restrict__ Ch, int ldc,
    const float* __restrict__ bias, const float* __restrict__ bias2,
    const float* __restrict__ xyz,
    __half* __restrict__ Gc,
    float* __restrict__ cst, __half* __restrict__ hout)
{
    extern __shared__ uint32_t smw[];
    const int tid = threadIdx.x, lane = tid & 31, wid = tid >> 5;
    const int wm = wid >> 1, wn = wid & 1;
    const int g = lane >> 2, t = lane & 3;
    const int m0 = blockIdx.y * BM;
    const int n0 = blockIdx.x * BN;
    const int j0 = blockIdx.x * 32;

    const int arow = tid >> 1, seg = tid & 1;
    int brow;
    if (MODE == 0 || MODE == 1) {
        int w = arow >> 6, cw = arow & 63;
        brow = (cw >> 4) * HID + j0 + (cw & 15) + (w << 4);
    } else brow = n0 + arow;

    const __half* aptr = A + (size_t)(m0 + arow) * lda + seg * 16;
    const __half* bptr = B + (size_t)brow * ldb + seg * 16;

    const uint32_t asb = (uint32_t)__cvta_generic_to_shared(smw);
    const uint32_t bsb = asb + NSTAGE * ABUF;
    const uint32_t aoff = asb + arow * (RS * 4) + seg * 32;
    const uint32_t boff = bsb + arow * (RS * 4) + seg * 32;

    const int lr = lane & 15, lw = (lane >> 4) * 16;
    uint32_t aadr[2], badr[4];
#pragma unroll
    for (int mt = 0; mt < 2; mt++)
        aadr[mt] = asb + (uint32_t)((wm * 32 + mt * 16 + lr) * RS * 4) + lw;
#pragma unroll
    for (int p = 0; p < 4; p++)
        badr[p] = bsb + (uint32_t)((wn * 64 + p * 16 + lr) * RS * 4) + lw;

    float acc[2][8][4];
#pragma unroll
    for (int i = 0; i < 2; i++)
#pragma unroll
        for (int j = 0; j < 8; j++)
#pragma unroll
            for (int k = 0; k < 4; k++) acc[i][j][k] = 0.f;

#define LOADTILE(IT, BUF)                                                     \
    do {                                                                      \
        cp16(aoff + (BUF) * ABUF, aptr + (IT) * BK);                          \
        cp16(aoff + (BUF) * ABUF + 16, aptr + (IT) * BK + 8);                 \
        cp16(boff + (BUF) * BBUF, bptr + (IT) * BK);                          \
        cp16(boff + (BUF) * BBUF + 16, bptr + (IT) * BK + 8);                 \
    } while (0)

    LOADTILE(0, 0);
    asm volatile("cp.async.commit_group;" ::: "memory");
    LOADTILE(1, 1);
    asm volatile("cp.async.commit_group;" ::: "memory");
    LOADTILE(2, 2);
    asm volatile("cp.async.commit_group;" ::: "memory");

#pragma unroll
    for (int it = 0; it < KITERS; ++it) {
        asm volatile("cp.async.wait_group 2;" ::: "memory");
        __syncthreads();
        if (it + 3 < KITERS) LOADTILE(it + 3, (it + 3) & (NSTAGE - 1));
        asm volatile("cp.async.commit_group;" ::: "memory");

        const uint32_t ao = (it & (NSTAGE - 1)) * ABUF;
        const uint32_t bo = (it & (NSTAGE - 1)) * BBUF;
#pragma unroll
        for (int ks = 0; ks < 2; ks++) {
            unsigned af[2][4];
            LDSM4(af[0], aadr[0] + ao + ks * 32);
            LDSM4(af[1], aadr[1] + ao + ks * 32);
#pragma unroll
            for (int p = 0; p < 4; p++) {
                unsigned bb[4];
                LDSM4(bb, badr[p] + bo + ks * 32);
                mma16(acc[0][2 * p],     af[0], bb[0], bb[2]);
                mma16(acc[0][2 * p + 1], af[0], bb[1], bb[3]);
                mma16(acc[1][2 * p],     af[1], bb[0], bb[2]);
                mma16(acc[1][2 * p + 1], af[1], bb[1], bb[3]);
            }
        }
    }
#undef LOADTILE

    // ----------------- epilogue -----------------
    if (MODE == 0 || MODE == 1) {
#pragma unroll
        for (int q = 0; q < 2; q++) {
            const int jc = j0 + wn * 16 + q * 8 + 2 * t;
            float4 wt[4][2];
            float bi[4][2];
#pragma unroll
            for (int e = 0; e < 2; e++) {
                const float4* wxp = (const float4*)(g_wx + (jc + e) * 16);
#pragma unroll
                for (int gt = 0; gt < 4; gt++) {
                    wt[gt][e] = wxp[gt];
                    if (MODE == 0)
                        bi[gt][e] = bias[gt * HID + jc + e] + bias2[gt * HID + jc + e];
                }
            }
#pragma unroll
            for (int mt = 0; mt < 2; mt++)
#pragma unroll
                for (int rr = 0; rr < 2; rr++) {
                    int r = m0 + wm * 32 + mt * 16 + g + rr * 8;
                    float x0 = xyz[r * 3], x1 = xyz[r * 3 + 1], x2 = xyz[r * 3 + 2];
                    float2 cn; __half2 hn;
                    __half* gcp = Gc + (size_t)r * NGATE + jc * 4;
                    if (MODE == 0) {
                        __align__(16) __half hg[8];
#pragma unroll
                        for (int e = 0; e < 2; e++) {
                            int a = rr * 2 + e;
                            float gcv[4], gate[4];
#pragma unroll
                            for (int gt = 0; gt < 4; gt++) {
                                gcv[gt] = acc[mt][2 * gt + q][a] + bi[gt][e];
                                gate[gt] = gcv[gt] + x0 * wt[gt][e].x
                                         + x1 * wt[gt][e].y + x2 * wt[gt][e].z;
                                hg[e * 4 + gt] = __float2half_rn(gcv[gt]);
                            }
                            float c2 = sigm(gate[0]) * tanhf(gate[2]);
                            __half h2 = __float2half_rn(sigm(gate[3]) * tanhf(c2));
                            if (e) { cn.y = c2; hn.y = h2; } else { cn.x = c2; hn.x = h2; }
                        }
                        *(uint4*)gcp = *(const uint4*)hg;
                    } else {
                        __align__(16) __half hg[8];
                        *(uint4*)hg = *(const uint4*)gcp;
                        float2 co = *(const float2*)(cst + (size_t)r * HID + jc);
#pragma unroll
                        for (int e = 0; e < 2; e++) {
                            int a = rr * 2 + e;
                            float iv = acc[mt][0 + q][a] + __half2float(hg[e * 4 + 0])
                                     + x0 * wt[0][e].x + x1 * wt[0][e].y + x2 * wt[0][e].z;
                            float fv = acc[mt][2 + q][a] + __half2float(hg[e * 4 + 1])
                                     + x0 * wt[1][e].x + x1 * wt[1][e].y + x2 * wt[1][e].z;
                            float gv = acc[mt][4 + q][a] + __half2float(hg[e * 4 + 2])
                                     + x0 * wt[2][e].x + x1 * wt[2][e].y + x2 * wt[2][e].z;
                            float ov = acc[mt][6 + q][a] + __half2float(hg[e * 4 + 3])
                                     + x0 * wt[3][e].x + x1 * wt[3][e].y + x2 * wt[3][e].z;
                            float cold = e ? co.y : co.x;
                            float c2 = sigm(fv) * cold + sigm(iv) * tanhf(gv);
                            __half h2 = __float2half_rn(sigm(ov) * tanhf(c2));
                            if (e) { cn.y = c2; hn.y = h2; } else { cn.x = c2; hn.x = h2; }
                        }
                    }
                    *(float2*)(cst + (size_t)r * HID + jc) = cn;
                    *(__half2*)(hout + (size_t)r * HID + jc) = hn;
                }
        }
    } else {
#pragma unroll
        for (int mt = 0; mt < 2; mt++)
#pragma unroll
            for (int nt = 0; nt < 8; nt++) {
                int c = n0 + wn * 64 + nt * 8 + 2 * t;
                float b0v = bias[c], b1v = bias[c + 1];
#pragma unroll
                for (int rr = 0; rr < 2; rr++) {
                    int r = m0 + wm * 32 + mt * 16 + g + rr * 8;
                    __half2 o;
                    o.x = __float2half_rn(fmaxf(acc[mt][nt][rr * 2 + 0] + b0v, 0.f));
                    o.y = __float2half_rn(fmaxf(acc[mt][nt][rr * 2 + 1] + b1v, 0.f));
                    *(__half2*)(Ch + (size_t)r * ldc + c) = o;
                }
            }
    }
}

// ------------------------- prep kernels -------------------------
__global__ void extract_code(const float* __restrict__ input,
                             const float* __restrict__ W_ih)
{
    int m = blockIdx.x, k = threadIdx.x;
    g_code[(size_t)m * 256 + k] = __float2half_rn(input[(size_t)m * DIN + k]);
    if (k < 3) g_xyz[m * 3 + k] = input[(size_t)m * DIN + 256 + k];
    if (m < HID && k < 16) {
        int gt = k >> 2, kk = k & 3;
        g_wx[m * 16 + gt * 4 + kk] =
            (kk < 3) ? W_ih[(size_t)(gt * HID + m) * DIN + 256 + kk] : 0.f;
    }
}
__global__ void prep_weights(const float* __restrict__ W_ih, const float* __restrict__ W_hh)
{
    int r = blockIdx.x, t = threadIdx.x;
    g_wih[(size_t)r * 256 + t] = __float2half_rn(W_ih[(size_t)r * DIN + t]);
    g_whh[(size_t)r * HID + t]       = __float2half_rn(W_hh[(size_t)r * HID + t]);
    g_whh[(size_t)r * HID + 256 + t] = __float2half_rn(W_hh[(size_t)r * HID + 256 + t]);
}
struct WnArgs { const float* v[5]; const float* g[5]; };
__global__ void wnorm_all(WnArgs wa)
{
    int layer = blockIdx.x >> 8, row = blockIdx.x & 255;
    int din = (layer == 0) ? 3 : 256;
    const float* vr = wa.v[layer] + (size_t)row * din;
    float s = 0.f;
    for (int k = threadIdx.x; k < din; k += blockDim.x) { float x = vr[k]; s += x * x; }
    __shared__ float red[4];
#pragma unroll
    for (int o = 16; o; o >>= 1) s += __shfl_xor_sync(0xffffffffu, s, o);
    if ((threadIdx.x & 31) == 0) red[threadIdx.x >> 5] = s;
    __syncthreads();
    float scale = wa.g[layer][row] / sqrtf(red[0] + red[1] + red[2] + red[3]);
    if (layer == 0) {
        for (int k = threadIdx.x; k < din; k += blockDim.x)
            g_w0[(size_t)row * din + k] = vr[k] * scale;
    } else {
        __half* w = g_wm + (size_t)(layer - 1) * 256 * 256 + (size_t)row * 256;
        for (int k = threadIdx.x; k < din; k += blockDim.x)
            w[k] = __float2half_rn(vr[k] * scale);
    }
}

// ------------------------- affine + xyz update -------------------------
__global__ __launch_bounds__(256) void affine_xyz(const __half* __restrict__ h_in,
                                                  const float* __restrict__ W_aff,
                                                  const float* __restrict__ b_aff)
{
    __shared__ float sW[6 * HID];
    for (int i = threadIdx.x; i < 6 * HID; i += 256) sW[i] = W_aff[i];
    __syncthreads();
    int warp = threadIdx.x >> 5, lane = threadIdx.x & 31;
    int m = blockIdx.x * 8 + warp;
    const __half* h = h_in + (size_t)m * HID;
    float p0 = 0, p1 = 0, p2 = 0, p3 = 0, p4 = 0, p5 = 0;
    for (int k = lane; k < HID; k += 32) {
        float hv = __half2float(h[k]);
        p0 += sW[k] * hv;           p1 += sW[HID + k] * hv;
        p2 += sW[2 * HID + k] * hv; p3 += sW[3 * HID + k] * hv;
        p4 += sW[4 * HID + k] * hv; p5 += sW[5 * HID + k] * hv;
    }
#pragma unroll
    for (int o = 16; o; o >>= 1) {
        p0 += __shfl_xor_sync(0xffffffffu, p0, o);
        p1 += __shfl_xor_sync(0xffffffffu, p1, o);
        p2 += __shfl_xor_sync(0xffffffffu, p2, o);
        p3 += __shfl_xor_sync(0xffffffffu, p3, o);
        p4 += __shfl_xor_sync(0xffffffffu, p4, o);
        p5 += __shfl_xor_sync(0xffffffffu, p5, o);
    }
    if (lane == 0) {
        float a0 = p0 + b_aff[0], a1 = p1 + b_aff[1], a2 = p2 + b_aff[2];
        float a3 = p3 + b_aff[3], a4 = p4 + b_aff[4], a5 = p5 + b_aff[5];
        float x0 = g_xyz[m * 3], x1 = g_xyz[m * 3 + 1], x2 = g_xyz[m * 3 + 2];
        g_xyz[m * 3 + 0] = a3 + (1.f + a0) * x0;
        g_xyz[m * 3 + 1] = a4 + (1.f + a1) * x1;
        g_xyz[m * 3 + 2] = a5 + (1.f + a2) * x2;
    }
}

// ------------------------- decoder layer 0 / final dot -------------------------
__global__ __launch_bounds__(256) void dec0(const float* __restrict__ b0)
{
    __shared__ float sw[768];
    __shared__ float sb[256];
    for (int i = threadIdx.x; i < 768; i += 256) sw[i] = g_w0[i];
    sb[threadIdx.x] = b0[threadIdx.x];
    __syncthreads();
    size_t idx = (size_t)blockIdx.x * 256 + threadIdx.x;
    int m = (int)(idx >> 8), i = (int)(idx & 255);
    float v = sw[i * 3] * g_xyz[m * 3] + sw[i * 3 + 1] * g_xyz[m * 3 + 1]
            + sw[i * 3 + 2] * g_xyz[m * 3 + 2] + sb[i];
    g_act0[idx] = __float2half_rn(fmaxf(v, 0.f));
}
__global__ __launch_bounds__(256) void dec5(const float* __restrict__ W5,
                                            const float* __restrict__ b5,
                                            const __half* __restrict__ x,
                                            float* __restrict__ out)
{
    __shared__ float sw[256];
    sw[threadIdx.x] = W5[threadIdx.x];
    __syncthreads();
    int warp = threadIdx.x >> 5, lane = threadIdx.x & 31;
    int m = blockIdx.x * 8 + warp;
    const __half* xr = x + (size_t)m * 256;
    float s = 0.f;
    for (int k = lane; k < 256; k += 32) s += __half2float(xr[k]) * sw[k];
#pragma unroll
    for (int o = 16; o; o >>= 1) s += __shfl_xor_sync(0xffffffffu, s, o);
    if (lane == 0) out[m] = s + b5[0];
}

// ------------------------- host launcher -------------------------
extern "C" void kernel_launch(void* const* d_in, const int* in_sizes, int n_in,
                              void* d_out, int out_size)
{
    const float* input = (const float*)d_in[0];
    const float* W_ih  = (const float*)d_in[1];
    const float* b_ih  = (const float*)d_in[2];
    const float* W_hh  = (const float*)d_in[3];
    const float* b_hh  = (const float*)d_in[4];
    const float* W_aff = (const float*)d_in[5];
    const float* b_aff = (const float*)d_in[6];
    WnArgs wa;
    const float* bb[5];
    for (int l = 0; l < 5; l++) {
        wa.v[l] = (const float*)d_in[7 + 3 * l];
        wa.g[l] = (const float*)d_in[8 + 3 * l];
        bb[l]   = (const float*)d_in[9 + 3 * l];
    }
    const float* W5 = (const float*)d_in[22];
    const float* b5 = (const float*)d_in[23];

    float *cst, *xyz;
    __half *Gc, *h0, *h1, *codep, *wihp, *whhp, *a0p, *a1p, *wmp;
    cudaGetSymbolAddress((void**)&Gc,    g_Gc);
    cudaGetSymbolAddress((void**)&h0,    g_h);
    cudaGetSymbolAddress((void**)&h1,    g_h2);
    cudaGetSymbolAddress((void**)&cst,   g_c);
    cudaGetSymbolAddress((void**)&xyz,   g_xyz);
    cudaGetSymbolAddress((void**)&codep, g_code);
    cudaGetSymbolAddress((void**)&wihp,  g_wih);
    cudaGetSymbolAddress((void**)&whhp,  g_whh);
    cudaGetSymbolAddress((void**)&a0p,   g_act0);
    cudaGetSymbolAddress((void**)&a1p,   g_act1);
    cudaGetSymbolAddress((void**)&wmp,   g_wm);

    const int SMEM = NSTAGE * (ABUF + BBUF);   // 81920 B per CTA
    cudaFuncSetAttribute((const void*)gemm_h<0, 8>,  cudaFuncAttributeMaxDynamicSharedMemorySize, SMEM);
    cudaFuncSetAttribute((const void*)gemm_h<1, 16>, cudaFuncAttributeMaxDynamicSharedMemorySize, SMEM);
    cudaFuncSetAttribute((const void*)gemm_h<2, 8>,  cudaFuncAttributeMaxDynamicSharedMemorySize, SMEM);

    extract_code<<<NSAMP, 256>>>(input, W_ih);
    prep_weights<<<NGATE, 256>>>(W_ih, W_hh);
    wnorm_all<<<1280, 128>>>(wa);

    // launch 3 (profiled): fused Gc GEMM + step-0 cell init
    gemm_h<0, 8><<<dim3(NGATE / BN, NSAMP / BM), 256, SMEM>>>(
        codep, 256, wihp, 256, nullptr, 0,
        b_ih, b_hh, xyz, Gc, cst, h0);

    affine_xyz<<<NSAMP / 8, 256>>>(h0, W_aff, b_aff);

    __half* hb[2] = { h0, h1 };
    for (int s = 1; s < 8; s++) {
        const __half* hin = hb[(s - 1) & 1];
        __half* hnew = hb[s & 1];
        gemm_h<1, 16><<<dim3(HID / 32, NSAMP / BM), 256, SMEM>>>(
            hin, HID, whhp, HID, nullptr, 0,
            nullptr, nullptr, xyz, Gc, cst, hnew);
        affine_xyz<<<NSAMP / 8, 256>>>(hnew, W_aff, b_aff);
    }

    dec0<<<NSAMP, 256>>>(bb[0]);
    const __half* bufin = a0p;
    __half* bufout = a1p;
    for (int l = 1; l < 5; l++) {
        gemm_h<2, 8><<<dim3(256 / BN, NSAMP / BM), 256, SMEM>>>(
            bufin, 256, wmp + (size_t)(l - 1) * 256 * 256, 256,
            bufout, 256,
            bb[l], nullptr, nullptr, nullptr, nullptr, nullptr);
        const __half* tmp = bufout; bufout = (__half*)bufin; bufin = tmp;
    }
    dec5<<<NSAMP / 8, 256>>>(W5, b5, bufin, (float*)d_out);
}